// round 2
// baseline (speedup 1.0000x reference)
#include <cuda_runtime.h>
#include <math.h>

#define BATCH 4096
#define NNEG 64
#define DIM 128
#define HID 512
#define MARGINF 24.0f
#define MROWS 32
#define KT 8            // W1 k-slice staged in shared per stage

// Scratch (allocation-free rule: __device__ globals). Written non-atomically
// each launch -> graph-replay safe, no zeroing needed.
__device__ float g_conf[BATCH];
__device__ float g_dpos[BATCH];
__device__ float g_negsp[BATCH];   // sum over negs of softplus(d_neg - MARGIN)

__device__ __forceinline__ float warp_sum(float v) {
#pragma unroll
    for (int o = 16; o; o >>= 1) v += __shfl_xor_sync(0xffffffffu, v, o);
    return v;
}

// stable softplus(z) = max(z,0) + log1p(exp(-|z|));  -log_sigmoid(x) = softplus(-x)
__device__ __forceinline__ float softplusf(float z) {
    return fmaxf(z, 0.f) + log1pf(expf(-fabsf(z)));
}

// ---------------------------------------------------------------------------
// Kernel 1: positive pass, register-tiled GEMM.
// 32 rows/block, 512 threads = 8 row-groups x 64 col-groups.
// Thread tile: 4 rows x 8 cols = 32 fp32 accumulators.
// Inner loop: 1 broadcast LDS.128 (A) + 2 LDS.128 (W) per 32 FMA.
// W1 staged through shared in KT=8 k-slices (coalesced LDG.128 -> STS).
// ---------------------------------------------------------------------------
__global__ __launch_bounds__(512, 1) void mlp_pos_kernel(
    const int* __restrict__ pos, const float* __restrict__ ent,
    const float* __restrict__ rel, const float* __restrict__ W1,
    const float* __restrict__ b1, const float* __restrict__ W2,
    const float* __restrict__ b2)
{
    __shared__ float shA[DIM][36];        // diff tile, [k][row], pitch 36 (16B-aligned rows)
    __shared__ float shW[KT][HID];        // W1 k-slice
    __shared__ int   sh_idx[MROWS][3];
    __shared__ float sh_part[MROWS][2];

    const int tid  = threadIdx.x;
    const int lane = tid & 31;
    const int wid  = tid >> 5;
    const int rg   = tid >> 6;            // row group 0..7  (4 rows each)
    const int cg   = tid & 63;            // col group 0..63 (8 cols each)
    const int row0 = blockIdx.x * MROWS;

    if (tid < MROWS * 3)
        sh_idx[tid / 3][tid % 3] = pos[(row0 + tid / 3) * 3 + (tid % 3)];
    __syncthreads();

    // gather + diff: consecutive tid -> consecutive k (coalesced 512B per row)
#pragma unroll
    for (int s = tid; s < MROWS * DIM; s += 512) {
        int row = s >> 7, k = s & 127;
        size_t h = (size_t)sh_idx[row][0];
        int    r = sh_idx[row][1];
        size_t t = (size_t)sh_idx[row][2];
        shA[k][row] = ent[h * DIM + k] + rel[(size_t)r * DIM + k] - ent[t * DIM + k];
    }
    __syncthreads();

    // d_pos: warp w handles rows 2w, 2w+1
#pragma unroll
    for (int rr = 0; rr < 2; rr++) {
        int row = wid * 2 + rr;
        float s = 0.f;
#pragma unroll
        for (int kk = 0; kk < 4; kk++) s += fabsf(shA[lane + kk * 32][row]);
        s = warp_sum(s);
        if (lane == 0) g_dpos[row0 + row] = s;
    }

    // Register-tiled GEMM: acc[4 rows][8 cols]
    float acc[4][8];
#pragma unroll
    for (int r = 0; r < 4; r++)
#pragma unroll
        for (int c = 0; c < 8; c++) acc[r][c] = 0.f;

    const float4* W1v = (const float4*)W1;

    for (int k0 = 0; k0 < DIM; k0 += KT) {
        __syncthreads();   // previous slice fully consumed
        // stage KT x 512 floats = 1024 float4; 512 threads x 2 float4 each
        {
            float4 v0 = W1v[(size_t)k0 * (HID / 4) + tid];
            float4 v1 = W1v[(size_t)k0 * (HID / 4) + 512 + tid];
            ((float4*)&shW[0][0])[tid]       = v0;
            ((float4*)&shW[0][0])[512 + tid] = v1;
        }
        __syncthreads();

#pragma unroll
        for (int kk = 0; kk < KT; kk++) {
            // A: 4 rows, warp-uniform broadcast
            float4 a4 = *(const float4*)&shA[k0 + kk][rg * 4];
            // W: 8 cols
            float4 w0 = *(const float4*)&shW[kk][cg * 8];
            float4 w1 = *(const float4*)&shW[kk][cg * 8 + 4];
            float wv[8] = {w0.x, w0.y, w0.z, w0.w, w1.x, w1.y, w1.z, w1.w};
            float av[4] = {a4.x, a4.y, a4.z, a4.w};
#pragma unroll
            for (int r = 0; r < 4; r++)
#pragma unroll
                for (int c = 0; c < 8; c++)
                    acc[r][c] = fmaf(av[r], wv[c], acc[r][c]);
        }
    }

    // epilogue: relu(acc + b1[j]) * W2[j], sum over this thread's 8 cols
    float bv[8], w2v[8];
#pragma unroll
    for (int c = 0; c < 8; c++) { bv[c] = b1[cg * 8 + c]; w2v[c] = W2[cg * 8 + c]; }

    float rowpart[4];
#pragma unroll
    for (int r = 0; r < 4; r++) {
        float s = 0.f;
#pragma unroll
        for (int c = 0; c < 8; c++)
            s += fmaxf(acc[r][c] + bv[c], 0.f) * w2v[c];
        rowpart[r] = s;
    }

    // reduce across the 64 col-groups: warp_sum (32 cg) -> 2 partials/row
    const int half = (cg >= 32);          // warp = rg*2 + half
#pragma unroll
    for (int r = 0; r < 4; r++) {
        float v = warp_sum(rowpart[r]);
        if (lane == 0) sh_part[rg * 4 + r][half] = v;
    }
    __syncthreads();
    if (tid < MROWS) {
        float s = b2[0] + sh_part[tid][0] + sh_part[tid][1];
        g_conf[row0 + tid] = 1.f / (1.f + expf(-s));
    }
}

// ---------------------------------------------------------------------------
// Kernel 2: negative pass. One block per batch row b, 8 warps, 8 negs/warp.
// One warp per triple: 32 lanes x float4 = coalesced 512B row gathers.
// ---------------------------------------------------------------------------
__global__ __launch_bounds__(256, 8) void neg_kernel(
    const int* __restrict__ negt, const float* __restrict__ ent,
    const float* __restrict__ rel)
{
    const int b    = blockIdx.x;
    const int lane = threadIdx.x & 31;
    const int wid  = threadIdx.x >> 5;
    __shared__ float sh[8];

    float local = 0.f;
#pragma unroll
    for (int n = wid; n < NNEG; n += 8) {
        int base = (b * NNEG + n) * 3;
        int hi = __ldg(negt + base);
        int ri = __ldg(negt + base + 1);
        int ti = __ldg(negt + base + 2);
        float4 a  = __ldg((const float4*)(ent + (size_t)hi * DIM) + lane);
        float4 rr = __ldg((const float4*)(rel + (size_t)ri * DIM) + lane);
        float4 c  = __ldg((const float4*)(ent + (size_t)ti * DIM) + lane);
        float s = fabsf(a.x + rr.x - c.x) + fabsf(a.y + rr.y - c.y)
                + fabsf(a.z + rr.z - c.z) + fabsf(a.w + rr.w - c.w);
        s = warp_sum(s);
        if (lane == 0) local += softplusf(s - MARGINF);
    }
    if (lane == 0) sh[wid] = local;
    __syncthreads();
    if (threadIdx.x == 0) {
        float t = 0.f;
#pragma unroll
        for (int w = 0; w < 8; w++) t += sh[w];
        g_negsp[b] = t;
    }
}

// ---------------------------------------------------------------------------
// Kernel 3: final combine + scalar reduce (double accumulation).
// ---------------------------------------------------------------------------
__global__ __launch_bounds__(512, 1) void final_kernel(float* __restrict__ out)
{
    __shared__ double sh[16];
    const int tid = threadIdx.x;
    double local = 0.0;
    for (int i = tid; i < BATCH; i += 512) {
        float pt = softplusf(g_dpos[i] - MARGINF);     // -log_sigmoid(M - d_pos)
        float nt = -g_negsp[i] * (1.f / NNEG);         // mean log_sigmoid(M - d_neg)
        local += (double)(g_conf[i] * (pt + nt));
    }
#pragma unroll
    for (int o = 16; o; o >>= 1) local += __shfl_xor_sync(0xffffffffu, local, o);
    const int lane = tid & 31, wid = tid >> 5;
    if (lane == 0) sh[wid] = local;
    __syncthreads();
    if (tid < 16) {
        double v = sh[tid];
#pragma unroll
        for (int o = 8; o; o >>= 1) v += __shfl_xor_sync(0x0000ffffu, v, o);
        if (tid == 0) out[0] = (float)v;
    }
}

// ---------------------------------------------------------------------------
extern "C" void kernel_launch(void* const* d_in, const int* in_sizes, int n_in,
                              void* d_out, int out_size)
{
    const int* pos = (const int*)d_in[0];
    const int* neg = (const int*)d_in[1];
    // negative_sample_size may or may not be materialized as input[2]
    const int o = (n_in >= 9) ? 1 : 0;
    const float* ent = (const float*)d_in[2 + o];
    const float* rel = (const float*)d_in[3 + o];
    const float* W1  = (const float*)d_in[4 + o];
    const float* b1  = (const float*)d_in[5 + o];
    const float* W2  = (const float*)d_in[6 + o];
    const float* b2  = (const float*)d_in[7 + o];
    float* out = (float*)d_out;

    mlp_pos_kernel<<<BATCH / MROWS, 512>>>(pos, ent, rel, W1, b1, W2, b2);
    neg_kernel<<<BATCH, 256>>>(neg, ent, rel);
    final_kernel<<<1, 512>>>(out);
}